// round 13
// baseline (speedup 1.0000x reference)
#include <cuda_runtime.h>
#include <math.h>

#define T_STEPS 512
#define BATCH   512
#define IN_DIM  4
#define AUX_DIM 28
#define OUT_DIM 32
#define G_DIM   64
#define NROWS   1184      // 128 (W_i) + 1024 (W_r) + 32 (W_o)
#define NCTA    128
#define NTHREADS 640
#define NGEMM   (NROWS / 2)   // 592 GEMM threads, 2 rows each
#define RX      280            // x-half rows resident in smem (tid < 140)

typedef unsigned long long ull;

// ---------------- device globals ----------------
__device__ float g_WcatT[G_DIM * NROWS];   // [g][row]
__device__ float g_bcat[NROWS];
__device__ float g_E[OUT_DIM * G_DIM];     // exp(W_s)        [o][g]
__device__ float g_sWr[G_DIM * OUT_DIM];   // sigmoid(W_rm.T) [g][o]
__device__ float g_d0[G_DIM];              // b0 @ exp(W_s)   [g]
__device__ ull   g_msg[2][NCTA * 4];       // (tag<<32)|float partial, 4 per CTA

__device__ __forceinline__ float sigm(float x) {
    return __fdividef(1.0f, 1.0f + __expf(-x));
}
__device__ __forceinline__ float tanh_fast(float x) {
    x = fminf(fmaxf(x, -12.0f), 12.0f);
    float e = __expf(2.0f * x);
    return __fdividef(e - 1.0f, e + 1.0f);
}
__device__ __forceinline__ float wsum32(float v) {
#pragma unroll
    for (int s = 16; s > 0; s >>= 1) v += __shfl_xor_sync(0xffffffffu, v, s);
    return v;
}
__device__ __forceinline__ void ffma2(ull& d, ull a, ull b) {
    asm("fma.rn.f32x2 %0, %1, %2, %0;" : "+l"(d) : "l"(a), "l"(b));
}
__device__ __forceinline__ ull dup2(float x) {
    ull r; asm("mov.b64 %0, {%1, %1};" : "=l"(r) : "f"(x)); return r;
}
__device__ __forceinline__ float2 unp(ull v) {
    float2 r;
    r.x = __uint_as_float((unsigned)v);
    r.y = __uint_as_float((unsigned)(v >> 32));
    return r;
}
__device__ __forceinline__ void ld_vol_v2u64(const ull* p, ull& a, ull& b) {
    asm volatile("ld.volatile.global.v2.u64 {%0, %1}, [%2];"
                 : "=l"(a), "=l"(b) : "l"(p) : "memory");
}

// one g-iter: feat pair (b0,b1),(b2,b3) vs 2-row weight -> 4 accs
#define GEMM_STEP(ACC, FF, W) do {                       \
    float2 _wf = unp(W);                                 \
    ull _w0 = dup2(_wf.x), _w1 = dup2(_wf.y);            \
    ffma2(ACC[0], FF.x, _w0); ffma2(ACC[1], FF.y, _w0);  \
    ffma2(ACC[2], FF.x, _w1); ffma2(ACC[3], FF.y, _w1);  \
} while (0)

// ---------------- prep ----------------
__global__ void prep_kernel(const float* __restrict__ W_i, const float* __restrict__ b_i,
                            const float* __restrict__ W_r, const float* __restrict__ b_r,
                            const float* __restrict__ W_o, const float* __restrict__ b_o,
                            const float* __restrict__ W_s, const float* __restrict__ W_rm,
                            const float* __restrict__ b0)
{
    int idx = blockIdx.x * blockDim.x + threadIdx.x;
    if (idx < G_DIM * NROWS) {
        int g = idx / NROWS, r = idx % NROWS;
        float v;
        if (r < 128)        v = W_i[r * G_DIM + g];
        else if (r < 1152)  v = W_r[(r - 128) * G_DIM + g];
        else                v = W_o[(r - 1152) * G_DIM + g];
        g_WcatT[idx] = v;
    }
    int i2 = idx - G_DIM * NROWS;
    if (i2 >= 0 && i2 < NROWS)
        g_bcat[i2] = (i2 < 128) ? b_i[i2] : (i2 < 1152) ? b_r[i2 - 128] : b_o[i2 - 1152];
    int i3 = i2 - NROWS;
    if (i3 >= 0 && i3 < OUT_DIM * G_DIM) g_E[i3] = expf(W_s[i3]);
    int i4 = i3 - OUT_DIM * G_DIM;
    if (i4 >= 0 && i4 < G_DIM * OUT_DIM) {
        int g = i4 / OUT_DIM, o = i4 % OUT_DIM;
        g_sWr[i4] = 1.0f / (1.0f + expf(-W_rm[o * G_DIM + g]));
    }
    int i5 = i4 - G_DIM * OUT_DIM;
    if (i5 >= 0 && i5 < G_DIM) {
        float a = 0.0f;
        for (int o = 0; o < OUT_DIM; ++o) a += b0[o] * expf(W_s[o * G_DIM + i5]);
        g_d0[i5] = a;
    }
    int i6 = i5 - G_DIM;
    if (i6 >= 0 && i6 < 2 * NCTA * 4) ((ull*)g_msg)[i6] = 0ull;
}

// ---------------- smem layout (float offsets) ----------------
#define OFF_WC    0                        // [32][1184] c-half weights (g=32..63)
#define OFF_WX    (OFF_WC + 32 * NROWS)    // 37888: [32][RX] x-half weights rows<RX
#define OFF_E     (OFF_WX + 32 * RX)       // 46848
#define OFF_SWR   (OFF_E + 2048)           // 48896
#define OFF_BC    (OFF_SWR + 2048)         // 50944
#define OFF_F1S   (OFF_BC + 1184)          // 52128: [2][32][4] double-buffered feat
#define OFF_CFS   (OFF_F1S + 256)          // 52384: [32][4] carry, g-major
#define OFF_GI    (OFF_CFS + 128)          // 52512: [4][128]
#define OFF_RR    (OFF_GI + 512)           // 53024: [4][1024]
#define OFF_OS    (OFF_RR + 4096)          // 57120: [4][32]
#define OFF_C     (OFF_OS + 128)           // 57248: [4][32]
#define OFF_XM    (OFF_C + 128)            // 57376: [2][4][4]
#define OFF_CR    (OFF_XM + 32)            // 57408: [4][32]
#define OFF_CI    (OFF_CR + 128)           // 57536: [4][4]
#define OFF_TH    (OFF_CI + 16)            // 57552: [4][64]
#define OFF_D0    (OFF_TH + 256)           // 57808: [64]
#define OFF_OV1   (OFF_D0 + 64)            // 57872: [4][32]
#define OFF_LNG   (OFF_OV1 + 128)          // 58000
#define OFF_LNB   (OFF_LNG + 32)           // 58032
#define OFF_MISC  (OFF_LNB + 32)           // 58064: [8]; [4]=S
#define SMEM_FLOATS (OFF_MISC + 8)         // 58072
#define SMEM_BYTES  (SMEM_FLOATS * 4)      // 232288 B (~226.8 KB)

__global__ void __launch_bounds__(NTHREADS, 1)
mclstm_kernel(const float* __restrict__ xm, const float* __restrict__ xa,
              const float* __restrict__ ln_g, const float* __restrict__ ln_b,
              float* __restrict__ out)
{
    extern __shared__ float sm[];
    float* Wc     = sm + OFF_WC;
    float* Wx     = sm + OFF_WX;
    float* E_s    = sm + OFF_E;
    float* sWr_s  = sm + OFF_SWR;
    float* bc_s   = sm + OFF_BC;
    float* f1s2   = sm + OFF_F1S;   // [2][128]
    float* cfs    = sm + OFF_CFS;
    float* gi_s   = sm + OFF_GI;
    float* rr_s   = sm + OFF_RR;
    float* o_s    = sm + OFF_OS;
    float* c_s    = sm + OFF_C;
    float* xm2    = sm + OFF_XM;    // [2][16]
    float* coef_r = sm + OFF_CR;
    float* coef_i = sm + OFF_CI;
    float* th_s   = sm + OFF_TH;
    float* d0_s   = sm + OFF_D0;
    float* ov1_s  = sm + OFF_OV1;
    float* lng_s  = sm + OFF_LNG;
    float* lnb_s  = sm + OFF_LNB;
    float* misc   = sm + OFF_MISC;

    const int tid = threadIdx.x;
    const int cta = blockIdx.x;
    const int bbase = cta * 4;
    const size_t OSTRIDE = (size_t)T_STEPS * BATCH * OUT_DIM;
    const int r0 = tid * 2;                 // GEMM rows for this thread

    // feeders: tid 512..639 (overlap GEMM warps 16-18 + poller warp 19)
    const bool feeder = (tid >= 512);
    int pb = 0, pg = 0;
    float xnext = 0.0f;
    if (feeder) {
        int idx = tid - 512;
        pb = idx >> 5; pg = idx & 31;
    }

    // ---- one-time smem fills ----
    for (int i = tid; i < 32 * NROWS; i += NTHREADS) {
        int g = i / NROWS, r = i - g * NROWS;
        Wc[i] = g_WcatT[(32 + g) * NROWS + r];
    }
    for (int i = tid; i < 32 * RX; i += NTHREADS) {
        int g = i / RX, r = i - g * RX;
        Wx[i] = g_WcatT[g * NROWS + r];
    }
    for (int i = tid; i < 2048; i += NTHREADS) { E_s[i] = g_E[i]; sWr_s[i] = g_sWr[i]; }
    for (int i = tid; i < NROWS; i += NTHREADS) bc_s[i] = g_bcat[i];
    if (tid < G_DIM) d0_s[tid] = g_d0[tid];
    if (tid < OUT_DIM) { lng_s[tid] = ln_g[tid]; lnb_s[tid] = ln_b[tid]; }
    if (tid < 128) { c_s[tid] = 0.0f; cfs[tid] = 0.0f; }
    if (tid < 8) misc[tid] = 0.0f;
    if (feeder) {
        // x(0) into buffer 0
        float x0 = (pg < IN_DIM) ? xm[(size_t)(bbase + pb) * IN_DIM + pg]
                                 : xa[(size_t)(bbase + pb) * AUX_DIM + (pg - IN_DIM)];
        f1s2[pg * 4 + pb] = x0;
        if (pg < IN_DIM) xm2[pb * 4 + pg] = x0;
        // x(1) into xnext
        xnext = (pg < IN_DIM) ? xm[((size_t)BATCH + bbase + pb) * IN_DIM + pg]
                              : xa[((size_t)BATCH + bbase + pb) * AUX_DIM + (pg - IN_DIM)];
    }
    __syncthreads();

    // ---- preamble: x-half GEMM for t=0 ----
    ull a1[4];
    {
#pragma unroll
        for (int k = 0; k < 4; ++k) a1[k] = 0ull;
        if (tid < NGEMM) {
            const ulonglong2* fU = (const ulonglong2*)f1s2;   // buffer 0
            if (tid < RX / 2) {
#pragma unroll 8
                for (int g = 0; g < 32; ++g) {
                    ulonglong2 ff = fU[g];
                    ull w = *(const ull*)(Wx + g * RX + r0);
                    GEMM_STEP(a1, ff, w);
                }
            } else {
#pragma unroll 4
                for (int g = 0; g < 32; ++g) {
                    ulonglong2 ff = fU[g];
                    ull w = __ldg((const ull*)(g_WcatT + g * NROWS + r0));
                    GEMM_STEP(a1, ff, w);
                }
            }
        }
    }

    for (int t = 0; t < T_STEPS; ++t) {
        __syncthreads();   // sync A: cfs/c_s ready; a1 holds x-half for step t

        const int bufn = (t + 1) & 1;
        // ---- feeders: commit x(t+1) into next buffer, then prefetch x(t+2) ----
        if (feeder) {
            f1s2[bufn * 128 + pg * 4 + pb] = xnext;
            if (pg < IN_DIM) xm2[bufn * 16 + pb * 4 + pg] = xnext;
            if (t + 2 < T_STEPS) {
                xnext = (pg < IN_DIM)
                    ? xm[((size_t)(t + 2) * BATCH + bbase + pb) * IN_DIM + pg]
                    : xa[((size_t)(t + 2) * BATCH + bbase + pb) * AUX_DIM + (pg - IN_DIM)];
            }
        }
        // ---- poller warp 19: gather 512 partials -> S (overlaps c-GEMM) ----
        if (t > 0 && tid >= 608) {
            const int lane = tid - 608;
            const unsigned tg = (unsigned)t;
            const ull* base = &g_msg[t & 1][lane * 16];
            float p;
            for (;;) {
                ull v[16];
#pragma unroll
                for (int k = 0; k < 8; ++k) ld_vol_v2u64(base + 2 * k, v[2 * k], v[2 * k + 1]);
                unsigned bad = 0;
#pragma unroll
                for (int k = 0; k < 16; ++k) bad |= ((unsigned)(v[k] >> 32)) ^ tg;
                if (bad == 0) {
                    float s0 = 0.f, s1 = 0.f;
#pragma unroll
                    for (int k = 0; k < 16; k += 2) {
                        s0 += __uint_as_float((unsigned)v[k]);
                        s1 += __uint_as_float((unsigned)v[k + 1]);
                    }
                    p = s0 + s1;
                    break;
                }
            }
            p = wsum32(p);
            if (lane == 0) misc[4] = p;
        }

        // ---- c-GEMM: carry vs Wc, ALL from smem ----
        ull a2[4];
        if (tid < NGEMM) {
#pragma unroll
            for (int k = 0; k < 4; ++k) a2[k] = 0ull;
            const ulonglong2* cU = (const ulonglong2*)cfs;
#pragma unroll 8
            for (int g = 0; g < 32; ++g) {
                ulonglong2 cc = cU[g];
                ull w = *(const ull*)(Wc + g * NROWS + r0);
                GEMM_STEP(a2, cc, w);
            }
        }
        __syncthreads();   // sync B: misc[4] (S) visible
        const float invS = __fdividef(1.0f, misc[4] + 1e-5f);

        // ---- combine: activations + coef reductions + th matvec ----
        float s[4];
        if (tid < NGEMM) {
            float2 bb = *(const float2*)&bc_s[r0];
            float2 A0 = unp(a1[0]), A1 = unp(a1[1]), A2 = unp(a1[2]), A3 = unp(a1[3]);
            float2 B0 = unp(a2[0]), B1 = unp(a2[1]), B2 = unp(a2[2]), B3 = unp(a2[3]);
            float p0[4], p1[4];
            p0[0] = fmaf(invS, B0.x, A0.x) + bb.x;
            p0[1] = fmaf(invS, B0.y, A0.y) + bb.x;
            p0[2] = fmaf(invS, B1.x, A1.x) + bb.x;
            p0[3] = fmaf(invS, B1.y, A1.y) + bb.x;
            p1[0] = fmaf(invS, B2.x, A2.x) + bb.y;
            p1[1] = fmaf(invS, B2.y, A2.y) + bb.y;
            p1[2] = fmaf(invS, B3.x, A3.x) + bb.y;
            p1[3] = fmaf(invS, B3.y, A3.y) + bb.y;
            if (r0 < 128) {
#pragma unroll
                for (int b = 0; b < 4; ++b) {
                    float v0 = sigm(p0[b]), v1 = sigm(p1[b]);
                    *(float2*)&gi_s[b * 128 + r0] = make_float2(v0, v1);
                    s[b] = v0 + v1;
                }
            } else if (r0 < 1152) {
#pragma unroll
                for (int b = 0; b < 4; ++b) {
                    float v0 = fmaxf(p0[b], 0.0f), v1 = fmaxf(p1[b], 0.0f);
                    *(float2*)&rr_s[b * 1024 + (r0 - 128)] = make_float2(v0, v1);
                    s[b] = v0 + v1;
                }
            } else {
#pragma unroll
                for (int b = 0; b < 4; ++b)
                    *(float2*)&o_s[b * 32 + (r0 - 1152)] =
                        make_float2(sigm(p0[b]), sigm(p1[b]));
            }
        }
        if (tid < 256) {   // th = tanh(invS * (c @ E) - d0)
            int b = tid >> 6, g = tid & 63;
            const float* cb = c_s + b * 32;
            float q0 = 0.f, q1 = 0.f;
#pragma unroll
            for (int o = 0; o < 32; o += 2) {
                q0 = fmaf(cb[o],     E_s[o * 64 + g],       q0);
                q1 = fmaf(cb[o + 1], E_s[(o + 1) * 64 + g], q1);
            }
            th_s[tid] = tanh_fast(fmaf(invS, q0 + q1, -d0_s[g]));
        }
        if (tid < 576) {   // half-warp reductions for coef denominators
#pragma unroll
            for (int sh = 1; sh <= 8; sh <<= 1) {
                s[0] += __shfl_xor_sync(0xffffffffu, s[0], sh);
                s[1] += __shfl_xor_sync(0xffffffffu, s[1], sh);
                s[2] += __shfl_xor_sync(0xffffffffu, s[2], sh);
                s[3] += __shfl_xor_sync(0xffffffffu, s[3], sh);
            }
            if ((tid & 15) == 0) {
                if (tid < 64) {
                    int ii = tid >> 4;
                    const float* xmb = xm2 + (t & 1) * 16;
#pragma unroll
                    for (int b = 0; b < 4; ++b)
                        coef_i[b * 4 + ii] = __fdividef(xmb[b * 4 + ii], fmaxf(s[b], 1e-12f));
                } else {
                    int n = (tid - 64) >> 4;
#pragma unroll
                    for (int b = 0; b < 4; ++b)
                        coef_r[b * 32 + n] = __fdividef(c_s[b * 32 + n], fmaxf(s[b], 1e-12f));
                }
            }
        }
        __syncthreads();   // sync C

        // ---- epilogue (warps 0-3: m; warps 12-15: LN) + x-GEMM(t+1) on all GEMM threads ----
        if (tid < 128) {
            int b = tid >> 5, o = tid & 31;
            float m0, m1, m2 = 0.f, m3 = 0.f;
            m0 = coef_i[b * 4 + 0] * gi_s[b * 128 + o]
               + coef_i[b * 4 + 1] * gi_s[b * 128 + 32 + o];
            m1 = coef_i[b * 4 + 2] * gi_s[b * 128 + 64 + o]
               + coef_i[b * 4 + 3] * gi_s[b * 128 + 96 + o];
#pragma unroll
            for (int n = 0; n < 32; n += 4) {
                m0 = fmaf(coef_r[b * 32 + n],     rr_s[b * 1024 + n * 32 + o],       m0);
                m1 = fmaf(coef_r[b * 32 + n + 1], rr_s[b * 1024 + (n + 1) * 32 + o], m1);
                m2 = fmaf(coef_r[b * 32 + n + 2], rr_s[b * 1024 + (n + 2) * 32 + o], m2);
                m3 = fmaf(coef_r[b * 32 + n + 3], rr_s[b * 1024 + (n + 3) * 32 + o], m3);
            }
            float m = (m0 + m1) + (m2 + m3);

            asm volatile("bar.sync 1, 256;" ::: "memory");   // join LN warps

            float og  = o_s[b * 32 + o];
            float ov1 = ov1_s[b * 32 + o];
            float f = 1.0f - og;
            float ov2 = ov1 - fmaxf(ov1 - f, 0.0f);
            float MR = fmaxf(ov2 + 1.0f - f, 0.0f) + f - 1.0f;
            float opr = og + MR;
            float h = og * m;
            float cnew = (1.0f - opr) * m;
            float mrf = MR * m;

            float a = wsum32(fabsf(cnew));
            if (o == 0) {
                ull msg = ((ull)(unsigned)(t + 1) << 32) | (ull)__float_as_uint(a);
                *((volatile ull*)&g_msg[(t + 1) & 1][cta * 4 + b]) = msg;
            }

            size_t base = ((size_t)t * BATCH + (bbase + b)) * OUT_DIM + o;
            out[base]               = h;
            out[OSTRIDE + base]     = cnew;
            out[2 * OSTRIDE + base] = og;
            out[3 * OSTRIDE + base] = MR;
            out[4 * OSTRIDE + base] = opr;
            out[5 * OSTRIDE + base] = mrf;
            out[6 * OSTRIDE + base] = h;

            c_s[b * 32 + o] = cnew;
            cfs[o * 4 + b]  = cnew;
        } else if (tid >= 384 && tid < 512) {
            int idx = tid - 384, b = idx >> 5, o = idx & 31;
            const float* thb = th_s + b * 64;
            float p0 = 0.f, p1 = 0.f, p2 = 0.f, p3 = 0.f;
#pragma unroll
            for (int g = 0; g < 64; g += 4) {
                p0 = fmaf(thb[g],     sWr_s[g * 32 + o],       p0);
                p1 = fmaf(thb[g + 1], sWr_s[(g + 1) * 32 + o], p1);
                p2 = fmaf(thb[g + 2], sWr_s[(g + 2) * 32 + o], p2);
                p3 = fmaf(thb[g + 3], sWr_s[(g + 3) * 32 + o], p3);
            }
            float pre = (p0 + p1) + (p2 + p3);
            float s1v = pre, s2v = pre * pre;
#pragma unroll
            for (int sft = 16; sft > 0; sft >>= 1) {
                s1v += __shfl_xor_sync(0xffffffffu, s1v, sft);
                s2v += __shfl_xor_sync(0xffffffffu, s2v, sft);
            }
            float mu  = s1v * (1.0f / 32.0f);
            float var = fmaxf(s2v * (1.0f / 32.0f) - mu * mu, 0.0f);
            ov1_s[idx] = (pre - mu) * rsqrtf(var + 1e-5f) * lng_s[o] + lnb_s[o];

            asm volatile("bar.sync 1, 256;" ::: "memory");   // release m warps
        }

        // ---- x-GEMM for step t+1 (overlaps epilogue / exchange latency) ----
        if (t + 1 < T_STEPS && tid < NGEMM) {
#pragma unroll
            for (int k = 0; k < 4; ++k) a1[k] = 0ull;
            const ulonglong2* fU = (const ulonglong2*)(f1s2 + bufn * 128);
            if (tid < RX / 2) {
#pragma unroll 8
                for (int g = 0; g < 32; ++g) {
                    ulonglong2 ff = fU[g];
                    ull w = *(const ull*)(Wx + g * RX + r0);
                    GEMM_STEP(a1, ff, w);
                }
            } else {
#pragma unroll 4
                for (int g = 0; g < 32; ++g) {
                    ulonglong2 ff = fU[g];
                    ull w = __ldg((const ull*)(g_WcatT + g * NROWS + r0));
                    GEMM_STEP(a1, ff, w);
                }
            }
        }
    }
}

// ---------------- launch ----------------
extern "C" void kernel_launch(void* const* d_in, const int* in_sizes, int n_in,
                              void* d_out, int out_size)
{
    const float* xm   = (const float*)d_in[0];
    const float* xa   = (const float*)d_in[1];
    const float* W_i  = (const float*)d_in[2];
    const float* b_i  = (const float*)d_in[3];
    const float* W_r  = (const float*)d_in[4];
    const float* b_r  = (const float*)d_in[5];
    const float* W_o  = (const float*)d_in[6];
    const float* b_o  = (const float*)d_in[7];
    const float* W_s  = (const float*)d_in[8];
    const float* W_rm = (const float*)d_in[9];
    const float* b0   = (const float*)d_in[10];
    const float* lng  = (const float*)d_in[11];
    const float* lnb  = (const float*)d_in[12];
    float* out = (float*)d_out;

    cudaFuncSetAttribute(mclstm_kernel, cudaFuncAttributeMaxDynamicSharedMemorySize, SMEM_BYTES);

    prep_kernel<<<320, 256>>>(W_i, b_i, W_r, b_r, W_o, b_o, W_s, W_rm, b0);
    mclstm_kernel<<<NCTA, NTHREADS, SMEM_BYTES>>>(xm, xa, lng, lnb, out);
}